// round 14
// baseline (speedup 1.0000x reference)
#include <cuda_runtime.h>
#include <cuda_fp16.h>
#include <cstdint>

#define B_  32
#define C_  32
#define H_  160
#define W_  160
#define TH  20
#define TW  20
#define NT  64
#define EPS 1e-5f
#define HW  (H_ * W_)        // 25600

#define NTHREADS 416         // 13 warps: 13 x T=2 = 26 m-tiles (25 real + 1 dummy)

// H tile: 484 rows (22x22 padded pixels), 80B stride (64B content: 32ch fp16)
#define HSTRIDE 80
#define H_BYTES (484 * HSTRIDE)        // 38720
// Weights: 288 rows (tap*32+ic), 80B stride (32 oc fp16 = 64B content)
#define W_BYTES (288 * HSTRIDE)        // 23040
#define SMEM_REQ (1024 + H_BYTES + W_BYTES + 256)   // 63040

__device__ float d_scale[NT * C_];
__device__ float d_shift[NT * C_];
// fp16 weights: [row = tap*32+ic][32 oc fp16]
__device__ __align__(16) __half g_w2[NT][288 * 32];

__device__ __forceinline__ uint32_t smem_u32(const void* p) {
    uint32_t a;
    asm("{ .reg .u64 t; cvta.to.shared.u64 t, %1; cvt.u32.u64 %0, t; }" : "=r"(a) : "l"(p));
    return a;
}

__device__ __forceinline__ void ldm_x4(uint32_t addr,
                                       uint32_t& r0, uint32_t& r1,
                                       uint32_t& r2, uint32_t& r3) {
    asm volatile("ldmatrix.sync.aligned.m8n8.x4.shared.b16 {%0,%1,%2,%3}, [%4];"
                 : "=r"(r0), "=r"(r1), "=r"(r2), "=r"(r3) : "r"(addr));
}
__device__ __forceinline__ void ldm_x4_t(uint32_t addr,
                                         uint32_t& r0, uint32_t& r1,
                                         uint32_t& r2, uint32_t& r3) {
    asm volatile("ldmatrix.sync.aligned.m8n8.x4.trans.shared.b16 {%0,%1,%2,%3}, [%4];"
                 : "=r"(r0), "=r"(r1), "=r"(r2), "=r"(r3) : "r"(addr));
}
__device__ __forceinline__ void mma16816(float* d, uint32_t a0, uint32_t a1,
                                         uint32_t a2, uint32_t a3,
                                         uint32_t b0, uint32_t b1) {
    asm volatile(
        "mma.sync.aligned.m16n8k16.row.col.f32.f16.f16.f32 "
        "{%0,%1,%2,%3},{%4,%5,%6,%7},{%8,%9},{%0,%1,%2,%3};"
        : "+f"(d[0]), "+f"(d[1]), "+f"(d[2]), "+f"(d[3])
        : "r"(a0), "r"(a1), "r"(a2), "r"(a3), "r"(b0), "r"(b1));
}

// ---------------------------------------------------------------------------
// Kernel 1: BN stats per (tile, channel=oc) + fp16 weight pack into g_w2.
// 512 threads, warp-shuffle reduction.
// ---------------------------------------------------------------------------
__global__ __launch_bounds__(512) void bn_stats_kernel(
    const float* __restrict__ x,
    const float* __restrict__ gamma,
    const float* __restrict__ beta,
    const float* __restrict__ conv_w)
{
    const int bid = blockIdx.x;           // t*32 + c
    const int t = bid >> 5;
    const int c = bid & 31;
    const int ti = t >> 3, tj = t & 7;
    const int tid = threadIdx.x;
    const int wid = tid >> 5;
    const int lane = tid & 31;

    const float* base = x + (size_t)c * HW + (size_t)(ti * TH) * W_ + tj * TW;
    const size_t bstride = (size_t)C_ * HW;

    float s = 0.f, s2 = 0.f;
    for (int i = tid; i < B_ * TH * 5; i += 512) {
        int b = i / (TH * 5);
        int r = i - b * (TH * 5);
        int y = r / 5, xq = r - y * 5;
        float4 v = *reinterpret_cast<const float4*>(
            &base[(size_t)b * bstride + y * W_ + xq * 4]);
        s  += (v.x + v.y) + (v.z + v.w);
        s2 += (v.x * v.x + v.y * v.y) + (v.z * v.z + v.w * v.w);
    }

    // weight pack for oc = c: row = tap*32 + ic
    for (int i = tid; i < 288; i += 512) {
        int ic = i / 9, tap = i - ic * 9;
        float w = conv_w[(((size_t)t * C_ + c) * C_ + ic) * 9 + tap];
        g_w2[t][(tap * 32 + ic) * 32 + c] = __float2half(w);
    }

    // warp-shuffle reduction
#pragma unroll
    for (int off = 16; off > 0; off >>= 1) {
        s  += __shfl_xor_sync(0xFFFFFFFFu, s,  off);
        s2 += __shfl_xor_sync(0xFFFFFFFFu, s2, off);
    }
    __shared__ float ws[16], ws2[16];
    if (lane == 0) { ws[wid] = s; ws2[wid] = s2; }
    __syncthreads();
    if (wid == 0) {
        s  = (lane < 16) ? ws[lane]  : 0.f;
        s2 = (lane < 16) ? ws2[lane] : 0.f;
#pragma unroll
        for (int off = 8; off > 0; off >>= 1) {
            s  += __shfl_xor_sync(0xFFFFFFFFu, s,  off);
            s2 += __shfl_xor_sync(0xFFFFFFFFu, s2, off);
        }
        if (lane == 0) {
            const float invN = 1.f / (float)(B_ * TH * TW);
            float mean = s * invN;
            float var  = s2 * invN - mean * mean;
            float sc = gamma[bid] * rsqrtf(var + EPS);
            d_scale[bid] = sc;
            d_shift[bid] = beta[bid] - mean * sc;
        }
    }
}

// ---------------------------------------------------------------------------
// Kernel 2: per-(tile, batch) implicit-GEMM 3x3 conv via fp16 mma.sync.
// 416 threads; T=2 balanced; B fragments software-pipelined by one stage.
// ---------------------------------------------------------------------------
__global__ __launch_bounds__(NTHREADS, 2) void conv_kernel(
    const float* __restrict__ x,
    const float* __restrict__ conv_b,
    float* __restrict__ out)
{
    extern __shared__ char smem[];
    const uint32_t sbase = smem_u32(smem);
    const uint32_t hb = (sbase + 1023u) & ~1023u;
    const uint32_t wb = hb + H_BYTES;
    char* hptr = smem + (hb - sbase);
    char* wptr = smem + (wb - sbase);
    float* sscale = reinterpret_cast<float*>(smem + (wb - sbase) + W_BYTES);
    float* sshift = sscale + 32;

    const int bid = blockIdx.x;     // t*32 + b
    const int t = bid >> 5;
    const int b = bid & 31;
    const int ti = t >> 3, tj = t & 7;
    const int tid = threadIdx.x;
    const int warp = tid >> 5;
    const int lane = tid & 31;

    // ---- stage BN params ----
    if (tid < 32) {
        sscale[tid] = d_scale[t * C_ + tid];
        sshift[tid] = d_shift[t * C_ + tid];
    }

    // ---- zero h region (halo must be 0) ----
    {
        uint4 z = make_uint4(0, 0, 0, 0);
        uint4* hz = reinterpret_cast<uint4*>(hptr);
        for (int i = tid; i < H_BYTES / 16; i += NTHREADS) hz[i] = z;
    }

    // ---- copy fp16 weights: 288 rows x 64B content (2 x 32B chunks) ----
    {
        const uint4* gsrc = reinterpret_cast<const uint4*>(g_w2[t]);
        uint4* wdst = reinterpret_cast<uint4*>(wptr);
        for (int i = tid; i < 288 * 2; i += NTHREADS) {
            int row = i >> 1, hf = i & 1;
            wdst[(row * HSTRIDE + hf * 32) >> 4]       = gsrc[(row * 64 + hf * 32) >> 4];
            wdst[((row * HSTRIDE + hf * 32) >> 4) + 1] = gsrc[((row * 64 + hf * 32) >> 4) + 1];
        }
    }
    __syncthreads();

    // ---- prologue: thread = 4 channels x 1 pixel -> one STS.64 ----
    const size_t xtile = ((size_t)b * C_) * HW + (size_t)(ti * TH) * W_ + tj * TW;
    for (int i = tid; i < 8 * TH * TW; i += NTHREADS) {   // 3200 work items
        int p  = i % 400;          // pixel
        int cq = i / 400;          // channel quad
        int py = p / 20, px = p - py * 20;
        int c0 = cq * 4;
        const float* xp = &x[xtile + (size_t)c0 * HW + py * W_ + px];
        uint32_t hrow = (uint32_t)((py + 1) * 22 + px + 1) * HSTRIDE;
        __half hq[4];
#pragma unroll
        for (int j = 0; j < 4; j++) {
            float f = fmaxf(fmaf(xp[(size_t)j * HW], sscale[c0 + j], sshift[c0 + j]), 0.f);
            hq[j] = __float2half(f);
        }
        *reinterpret_cast<uint64_t*>(hptr + hrow + cq * 8) = *reinterpret_cast<uint64_t*>(hq);
    }
    __syncthreads();

    // ---- warp-level implicit GEMM: warp w owns tiles {2w, 2w+1} ----
    const int li   = lane & 7;
    const int sel8 = (lane >> 3) & 1;
    const int selk = (lane >> 4) & 1;
    const int tg   = lane & 3;
    const int g    = lane >> 2;

    const int mt0 = 2 * warp;
    const int mt1 = mt0 + 1;

    // lane A-row base (padded coords) per tile; clamp dummy tile 25 into range
    int pr0, pr1;
    {
        int m = mt0 * 16 + li + sel8 * 8;
        int my = m / 20;
        pr0 = my * 22 + (m - my * 20);
    }
    {
        int mm = mt1 * 16 + li + sel8 * 8;
        if (mm > 399) mm = 399;
        int my = mm / 20;
        pr1 = my * 22 + (mm - my * 20);
    }
    const uint32_t arow0_base = hb + (uint32_t)pr0 * HSTRIDE;
    const uint32_t arow1_base = hb + (uint32_t)pr1 * HSTRIDE;

    float acc0[4][4], acc1[4][4];
#pragma unroll
    for (int j = 0; j < 4; j++)
#pragma unroll
        for (int k = 0; k < 4; k++) { acc0[j][k] = 0.f; acc1[j][k] = 0.f; }

    // flat it = tap*2 + kc; B smem row for it is exactly it*16
    const uint32_t bbase = wb + (uint32_t)(li + sel8 * 8) * HSTRIDE
                         + (uint32_t)selk * 16;
    const uint32_t ca_even = (uint32_t)selk * 16;        // kc=0
    const uint32_t ca_odd  = (uint32_t)(2 + selk) * 16;  // kc=1

    // prefetch B for it=0
    uint32_t bfA[8];
    ldm_x4_t(bbase,      bfA[0], bfA[1], bfA[2], bfA[3]);
    ldm_x4_t(bbase + 32, bfA[4], bfA[5], bfA[6], bfA[7]);

#pragma unroll 1
    for (int it = 0; it < 18; it++) {
        const int tap = it >> 1;
        const int q   = (tap * 11) >> 5;            // tap / 3
        const int dyx = q * 19 + tap;               // (tap/3)*22 + tap%3
        const uint32_t ca = (it & 1) ? ca_odd : ca_even;
        const uint32_t aoff = (uint32_t)dyx * HSTRIDE + ca;

        // issue both A loads, then next-B prefetch, then MMAs
        uint32_t a00, a01, a02, a03, a10, a11, a12, a13;
        ldm_x4(arow0_base + aoff, a00, a01, a02, a03);
        ldm_x4(arow1_base + aoff, a10, a11, a12, a13);

        uint32_t bfB[8];
        if (it < 17) {
            const uint32_t nb = bbase + (uint32_t)(it + 1) * (16 * HSTRIDE);
            ldm_x4_t(nb,      bfB[0], bfB[1], bfB[2], bfB[3]);
            ldm_x4_t(nb + 32, bfB[4], bfB[5], bfB[6], bfB[7]);
        }

#pragma unroll
        for (int j = 0; j < 4; j++)
            mma16816(acc0[j], a00, a01, a02, a03, bfA[2 * j], bfA[2 * j + 1]);
#pragma unroll
        for (int j = 0; j < 4; j++)
            mma16816(acc1[j], a10, a11, a12, a13, bfA[2 * j], bfA[2 * j + 1]);

        if (it < 17) {
#pragma unroll
            for (int k = 0; k < 8; k++) bfA[k] = bfB[k];
        }
    }

    // ---- epilogue: + bias + residual (skip dummy tile 25) ----
    const size_t bb = (size_t)b * C_ * HW;
    const int gtile = (ti * TH) * W_ + tj * TW;

    float cb0[4], cb1[4];
#pragma unroll
    for (int j = 0; j < 4; j++) {
        cb0[j] = conv_b[t * C_ + j * 8 + 2 * tg];
        cb1[j] = conv_b[t * C_ + j * 8 + 2 * tg + 1];
    }

#pragma unroll 1
    for (int tt = 0; tt < 2; tt++) {
        const int mt = (tt == 0) ? mt0 : mt1;
        const int m0 = mt * 16;
        if (m0 >= 400) break;                    // dummy tile: no stores
        const int p0 = m0 + g;
        const int p1 = p0 + 8;
        const int y0 = p0 / 20, x0 = p0 - y0 * 20;
        const int y1 = p1 / 20, x1 = p1 - y1 * 20;
        const size_t pa0 = (size_t)(gtile + y0 * W_ + x0);
        const size_t pa1 = (size_t)(gtile + y1 * W_ + x1);
        float (*ac)[4] = (tt == 0) ? acc0 : acc1;
#pragma unroll
        for (int j = 0; j < 4; j++) {
            const int oc = j * 8 + 2 * tg;
            const size_t a00 = bb + (size_t)oc * HW + pa0;
            const size_t a10 = bb + (size_t)oc * HW + pa1;
            out[a00]      = ac[j][0] + cb0[j] + x[a00];
            out[a00 + HW] = ac[j][1] + cb1[j] + x[a00 + HW];
            out[a10]      = ac[j][2] + cb0[j] + x[a10];
            out[a10 + HW] = ac[j][3] + cb1[j] + x[a10 + HW];
        }
    }
}

// ---------------------------------------------------------------------------
extern "C" void kernel_launch(void* const* d_in, const int* in_sizes, int n_in,
                              void* d_out, int out_size)
{
    const float* x      = (const float*)d_in[0];
    const float* gamma  = (const float*)d_in[1];
    const float* beta   = (const float*)d_in[2];
    const float* conv_w = (const float*)d_in[3];
    const float* conv_b = (const float*)d_in[4];
    float* out = (float*)d_out;

    bn_stats_kernel<<<NT * C_, 512>>>(x, gamma, beta, conv_w);

    cudaFuncSetAttribute(conv_kernel,
                         cudaFuncAttributeMaxDynamicSharedMemorySize, SMEM_REQ);
    conv_kernel<<<NT * B_, NTHREADS, SMEM_REQ>>>(x, conv_b, out);
}

// round 16
// speedup vs baseline: 1.0401x; 1.0401x over previous
#include <cuda_runtime.h>
#include <cuda_fp16.h>
#include <cstdint>

#define B_  32
#define C_  32
#define H_  160
#define W_  160
#define TH  20
#define TW  20
#define NT  64
#define EPS 1e-5f
#define HW  (H_ * W_)        // 25600

#define NTHREADS 416         // 13 warps: 13 x T=2 = 26 m-tiles (25 real + 1 dummy)

// H tile: 484 rows (22x22 padded pixels), 80B stride (64B content: 32ch fp16)
#define HSTRIDE 80
#define H_BYTES (484 * HSTRIDE)        // 38720
// Weights: 288 rows (tap*32+ic), 80B stride (32 oc fp16 = 64B content)
#define W_BYTES (288 * HSTRIDE)        // 23040
#define SMEM_REQ (1024 + H_BYTES + W_BYTES + 256)   // 63040

__device__ float d_scale[NT * C_];
__device__ float d_shift[NT * C_];
// fp16 weights: [row = tap*32+ic][32 oc fp16]
__device__ __align__(16) __half g_w2[NT][288 * 32];

__device__ __forceinline__ uint32_t smem_u32(const void* p) {
    uint32_t a;
    asm("{ .reg .u64 t; cvta.to.shared.u64 t, %1; cvt.u32.u64 %0, t; }" : "=r"(a) : "l"(p));
    return a;
}

__device__ __forceinline__ void ldm_x4(uint32_t addr,
                                       uint32_t& r0, uint32_t& r1,
                                       uint32_t& r2, uint32_t& r3) {
    asm volatile("ldmatrix.sync.aligned.m8n8.x4.shared.b16 {%0,%1,%2,%3}, [%4];"
                 : "=r"(r0), "=r"(r1), "=r"(r2), "=r"(r3) : "r"(addr));
}
__device__ __forceinline__ void ldm_x4_t(uint32_t addr,
                                         uint32_t& r0, uint32_t& r1,
                                         uint32_t& r2, uint32_t& r3) {
    asm volatile("ldmatrix.sync.aligned.m8n8.x4.trans.shared.b16 {%0,%1,%2,%3}, [%4];"
                 : "=r"(r0), "=r"(r1), "=r"(r2), "=r"(r3) : "r"(addr));
}
__device__ __forceinline__ void mma16816(float* d, uint32_t a0, uint32_t a1,
                                         uint32_t a2, uint32_t a3,
                                         uint32_t b0, uint32_t b1) {
    asm volatile(
        "mma.sync.aligned.m16n8k16.row.col.f32.f16.f16.f32 "
        "{%0,%1,%2,%3},{%4,%5,%6,%7},{%8,%9},{%0,%1,%2,%3};"
        : "+f"(d[0]), "+f"(d[1]), "+f"(d[2]), "+f"(d[3])
        : "r"(a0), "r"(a1), "r"(a2), "r"(a3), "r"(b0), "r"(b1));
}

// ---------------------------------------------------------------------------
// Kernel 1: BN stats per (tile, channel=oc) + fp16 weight pack into g_w2.
// 256 threads, warp-shuffle reduction.
// ---------------------------------------------------------------------------
__global__ __launch_bounds__(256) void bn_stats_kernel(
    const float* __restrict__ x,
    const float* __restrict__ gamma,
    const float* __restrict__ beta,
    const float* __restrict__ conv_w)
{
    const int bid = blockIdx.x;           // t*32 + c
    const int t = bid >> 5;
    const int c = bid & 31;
    const int ti = t >> 3, tj = t & 7;
    const int tid = threadIdx.x;
    const int wid = tid >> 5;
    const int lane = tid & 31;

    const float* base = x + (size_t)c * HW + (size_t)(ti * TH) * W_ + tj * TW;
    const size_t bstride = (size_t)C_ * HW;

    float s = 0.f, s2 = 0.f;
    for (int i = tid; i < B_ * TH * 5; i += 256) {
        int b = i / (TH * 5);
        int r = i - b * (TH * 5);
        int y = r / 5, xq = r - y * 5;
        float4 v = *reinterpret_cast<const float4*>(
            &base[(size_t)b * bstride + y * W_ + xq * 4]);
        s  += (v.x + v.y) + (v.z + v.w);
        s2 += (v.x * v.x + v.y * v.y) + (v.z * v.z + v.w * v.w);
    }

    // weight pack for oc = c: row = tap*32 + ic
    for (int i = tid; i < 288; i += 256) {
        int ic = i / 9, tap = i - ic * 9;
        float w = conv_w[(((size_t)t * C_ + c) * C_ + ic) * 9 + tap];
        g_w2[t][(tap * 32 + ic) * 32 + c] = __float2half(w);
    }

    // warp-shuffle reduction
#pragma unroll
    for (int off = 16; off > 0; off >>= 1) {
        s  += __shfl_xor_sync(0xFFFFFFFFu, s,  off);
        s2 += __shfl_xor_sync(0xFFFFFFFFu, s2, off);
    }
    __shared__ float ws[8], ws2[8];
    if (lane == 0) { ws[wid] = s; ws2[wid] = s2; }
    __syncthreads();
    if (wid == 0) {
        s  = (lane < 8) ? ws[lane]  : 0.f;
        s2 = (lane < 8) ? ws2[lane] : 0.f;
#pragma unroll
        for (int off = 4; off > 0; off >>= 1) {
            s  += __shfl_xor_sync(0xFFFFFFFFu, s,  off);
            s2 += __shfl_xor_sync(0xFFFFFFFFu, s2, off);
        }
        if (lane == 0) {
            const float invN = 1.f / (float)(B_ * TH * TW);
            float mean = s * invN;
            float var  = s2 * invN - mean * mean;
            float sc = gamma[bid] * rsqrtf(var + EPS);
            d_scale[bid] = sc;
            d_shift[bid] = beta[bid] - mean * sc;
        }
    }
}

// ---------------------------------------------------------------------------
// Kernel 2: per-(tile, batch) implicit-GEMM 3x3 conv via fp16 mma.sync.
// 416 threads; T=2 balanced; main loop FULLY UNROLLED (compile-time
// addresses -> ptxas self-pipelines LDSM across MMA groups, no reg copies).
// ---------------------------------------------------------------------------
__global__ __launch_bounds__(NTHREADS, 2) void conv_kernel(
    const float* __restrict__ x,
    const float* __restrict__ conv_b,
    float* __restrict__ out)
{
    extern __shared__ char smem[];
    const uint32_t sbase = smem_u32(smem);
    const uint32_t hb = (sbase + 1023u) & ~1023u;
    const uint32_t wb = hb + H_BYTES;
    char* hptr = smem + (hb - sbase);
    char* wptr = smem + (wb - sbase);
    float* sscale = reinterpret_cast<float*>(smem + (wb - sbase) + W_BYTES);
    float* sshift = sscale + 32;

    const int bid = blockIdx.x;     // t*32 + b
    const int t = bid >> 5;
    const int b = bid & 31;
    const int ti = t >> 3, tj = t & 7;
    const int tid = threadIdx.x;
    const int warp = tid >> 5;
    const int lane = tid & 31;

    // ---- stage BN params ----
    if (tid < 32) {
        sscale[tid] = d_scale[t * C_ + tid];
        sshift[tid] = d_shift[t * C_ + tid];
    }

    // ---- zero h region (halo must be 0) ----
    {
        uint4 z = make_uint4(0, 0, 0, 0);
        uint4* hz = reinterpret_cast<uint4*>(hptr);
        for (int i = tid; i < H_BYTES / 16; i += NTHREADS) hz[i] = z;
    }

    // ---- copy fp16 weights: 288 rows x 64B content (2 x 32B chunks) ----
    {
        const uint4* gsrc = reinterpret_cast<const uint4*>(g_w2[t]);
        uint4* wdst = reinterpret_cast<uint4*>(wptr);
        for (int i = tid; i < 288 * 2; i += NTHREADS) {
            int row = i >> 1, hf = i & 1;
            wdst[(row * HSTRIDE + hf * 32) >> 4]       = gsrc[(row * 64 + hf * 32) >> 4];
            wdst[((row * HSTRIDE + hf * 32) >> 4) + 1] = gsrc[((row * 64 + hf * 32) >> 4) + 1];
        }
    }
    __syncthreads();

    // ---- prologue: thread = 4 channels x 1 pixel -> one STS.64 ----
    const size_t xtile = ((size_t)b * C_) * HW + (size_t)(ti * TH) * W_ + tj * TW;
    for (int i = tid; i < 8 * TH * TW; i += NTHREADS) {   // 3200 work items
        int p  = i % 400;          // pixel
        int cq = i / 400;          // channel quad
        int py = p / 20, px = p - py * 20;
        int c0 = cq * 4;
        const float* xp = &x[xtile + (size_t)c0 * HW + py * W_ + px];
        uint32_t hrow = (uint32_t)((py + 1) * 22 + px + 1) * HSTRIDE;
        __half hq[4];
#pragma unroll
        for (int j = 0; j < 4; j++) {
            float f = fmaxf(fmaf(xp[(size_t)j * HW], sscale[c0 + j], sshift[c0 + j]), 0.f);
            hq[j] = __float2half(f);
        }
        *reinterpret_cast<uint64_t*>(hptr + hrow + cq * 8) = *reinterpret_cast<uint64_t*>(hq);
    }
    __syncthreads();

    // ---- warp-level implicit GEMM: warp w owns tiles {2w, 2w+1} ----
    const int li   = lane & 7;
    const int sel8 = (lane >> 3) & 1;
    const int selk = (lane >> 4) & 1;
    const int tg   = lane & 3;
    const int g    = lane >> 2;

    const int mt0 = 2 * warp;
    const int mt1 = mt0 + 1;

    int pr0, pr1;
    {
        int m = mt0 * 16 + li + sel8 * 8;
        int my = m / 20;
        pr0 = my * 22 + (m - my * 20);
    }
    {
        int mm = mt1 * 16 + li + sel8 * 8;
        if (mm > 399) mm = 399;                  // dummy tile 25: clamp reads
        int my = mm / 20;
        pr1 = my * 22 + (mm - my * 20);
    }
    const uint32_t arow0_base = hb + (uint32_t)pr0 * HSTRIDE;
    const uint32_t arow1_base = hb + (uint32_t)pr1 * HSTRIDE;

    float acc0[4][4], acc1[4][4];
#pragma unroll
    for (int j = 0; j < 4; j++)
#pragma unroll
        for (int k = 0; k < 4; k++) { acc0[j][k] = 0.f; acc1[j][k] = 0.f; }

    const uint32_t bbase = wb + (uint32_t)(li + sel8 * 8) * HSTRIDE
                         + (uint32_t)selk * 16;
    const uint32_t ca_sel = (uint32_t)selk * 16;

    // ---- FULLY UNROLLED main loop: it = tap*2 + kc, 18 iterations ----
#pragma unroll
    for (int it = 0; it < 18; it++) {
        const int tap = it >> 1;
        const int kc  = it & 1;
        const uint32_t dyx  = (uint32_t)((tap / 3) * 22 + (tap % 3));   // constant
        const uint32_t aoff = dyx * HSTRIDE + (uint32_t)(kc * 32) + ca_sel;
        const uint32_t boff = (uint32_t)it * (16 * HSTRIDE);            // constant

        uint32_t bf[8];
        ldm_x4_t(bbase + boff,      bf[0], bf[1], bf[2], bf[3]);
        ldm_x4_t(bbase + boff + 32, bf[4], bf[5], bf[6], bf[7]);

        uint32_t a00, a01, a02, a03, a10, a11, a12, a13;
        ldm_x4(arow0_base + aoff, a00, a01, a02, a03);
        ldm_x4(arow1_base + aoff, a10, a11, a12, a13);

#pragma unroll
        for (int j = 0; j < 4; j++)
            mma16816(acc0[j], a00, a01, a02, a03, bf[2 * j], bf[2 * j + 1]);
#pragma unroll
        for (int j = 0; j < 4; j++)
            mma16816(acc1[j], a10, a11, a12, a13, bf[2 * j], bf[2 * j + 1]);
    }

    // ---- epilogue: + bias + residual (skip dummy tile 25) ----
    const size_t bb = (size_t)b * C_ * HW;
    const int gtile = (ti * TH) * W_ + tj * TW;

    float cb0[4], cb1[4];
#pragma unroll
    for (int j = 0; j < 4; j++) {
        cb0[j] = conv_b[t * C_ + j * 8 + 2 * tg];
        cb1[j] = conv_b[t * C_ + j * 8 + 2 * tg + 1];
    }

#pragma unroll 1
    for (int tt = 0; tt < 2; tt++) {
        const int mt = (tt == 0) ? mt0 : mt1;
        const int m0 = mt * 16;
        if (m0 >= 400) break;                    // dummy tile: no stores
        const int p0 = m0 + g;
        const int p1 = p0 + 8;
        const int y0 = p0 / 20, x0 = p0 - y0 * 20;
        const int y1 = p1 / 20, x1 = p1 - y1 * 20;
        const size_t pa0 = (size_t)(gtile + y0 * W_ + x0);
        const size_t pa1 = (size_t)(gtile + y1 * W_ + x1);
        float (*ac)[4] = (tt == 0) ? acc0 : acc1;
#pragma unroll
        for (int j = 0; j < 4; j++) {
            const int oc = j * 8 + 2 * tg;
            const size_t a00 = bb + (size_t)oc * HW + pa0;
            const size_t a10 = bb + (size_t)oc * HW + pa1;
            out[a00]      = ac[j][0] + cb0[j] + x[a00];
            out[a00 + HW] = ac[j][1] + cb1[j] + x[a00 + HW];
            out[a10]      = ac[j][2] + cb0[j] + x[a10];
            out[a10 + HW] = ac[j][3] + cb1[j] + x[a10 + HW];
        }
    }
}

// ---------------------------------------------------------------------------
extern "C" void kernel_launch(void* const* d_in, const int* in_sizes, int n_in,
                              void* d_out, int out_size)
{
    const float* x      = (const float*)d_in[0];
    const float* gamma  = (const float*)d_in[1];
    const float* beta   = (const float*)d_in[2];
    const float* conv_w = (const float*)d_in[3];
    const float* conv_b = (const float*)d_in[4];
    float* out = (float*)d_out;

    bn_stats_kernel<<<NT * C_, 256>>>(x, gamma, beta, conv_w);

    cudaFuncSetAttribute(conv_kernel,
                         cudaFuncAttributeMaxDynamicSharedMemorySize, SMEM_REQ);
    conv_kernel<<<NT * B_, NTHREADS, SMEM_REQ>>>(x, conv_b, out);
}

// round 17
// speedup vs baseline: 1.0763x; 1.0349x over previous
#include <cuda_runtime.h>
#include <cuda_fp16.h>
#include <cstdint>

#define B_  32
#define C_  32
#define H_  160
#define W_  160
#define TH  20
#define TW  20
#define NT  64
#define EPS 1e-5f
#define HW  (H_ * W_)        // 25600

#define NTHREADS 416         // 13 warps: 13 x T=2 = 26 m-tiles (25 real + 1 dummy)

// H tile: 484 rows (22x22 padded pixels), 80B stride (64B content: 32ch fp16)
#define HSTRIDE 80
#define H_BYTES (484 * HSTRIDE)        // 38720
// Weights: 288 rows (tap*32+ic), 80B stride (32 oc fp16 = 64B content)
#define W_BYTES (288 * HSTRIDE)        // 23040
#define SMEM_REQ (1024 + H_BYTES + W_BYTES + 384)   // 63168

#define STG_STRIDE 404       // floats; (2*tg*404*4) banks -> conflict-free

__device__ float d_scale[NT * C_];
__device__ float d_shift[NT * C_];
// fp16 weights: [row = tap*32+ic][32 oc fp16]
__device__ __align__(16) __half g_w2[NT][288 * 32];

__device__ __forceinline__ uint32_t smem_u32(const void* p) {
    uint32_t a;
    asm("{ .reg .u64 t; cvta.to.shared.u64 t, %1; cvt.u32.u64 %0, t; }" : "=r"(a) : "l"(p));
    return a;
}

__device__ __forceinline__ void ldm_x4(uint32_t addr,
                                       uint32_t& r0, uint32_t& r1,
                                       uint32_t& r2, uint32_t& r3) {
    asm volatile("ldmatrix.sync.aligned.m8n8.x4.shared.b16 {%0,%1,%2,%3}, [%4];"
                 : "=r"(r0), "=r"(r1), "=r"(r2), "=r"(r3) : "r"(addr));
}
__device__ __forceinline__ void ldm_x4_t(uint32_t addr,
                                         uint32_t& r0, uint32_t& r1,
                                         uint32_t& r2, uint32_t& r3) {
    asm volatile("ldmatrix.sync.aligned.m8n8.x4.trans.shared.b16 {%0,%1,%2,%3}, [%4];"
                 : "=r"(r0), "=r"(r1), "=r"(r2), "=r"(r3) : "r"(addr));
}
__device__ __forceinline__ void mma16816(float* d, uint32_t a0, uint32_t a1,
                                         uint32_t a2, uint32_t a3,
                                         uint32_t b0, uint32_t b1) {
    asm volatile(
        "mma.sync.aligned.m16n8k16.row.col.f32.f16.f16.f32 "
        "{%0,%1,%2,%3},{%4,%5,%6,%7},{%8,%9},{%0,%1,%2,%3};"
        : "+f"(d[0]), "+f"(d[1]), "+f"(d[2]), "+f"(d[3])
        : "r"(a0), "r"(a1), "r"(a2), "r"(a3), "r"(b0), "r"(b1));
}

// ---------------------------------------------------------------------------
// Kernel 1: BN stats per (tile, channel=oc) + fp16 weight pack into g_w2.
// ---------------------------------------------------------------------------
__global__ __launch_bounds__(256) void bn_stats_kernel(
    const float* __restrict__ x,
    const float* __restrict__ gamma,
    const float* __restrict__ beta,
    const float* __restrict__ conv_w)
{
    const int bid = blockIdx.x;           // t*32 + c
    const int t = bid >> 5;
    const int c = bid & 31;
    const int ti = t >> 3, tj = t & 7;
    const int tid = threadIdx.x;
    const int wid = tid >> 5;
    const int lane = tid & 31;

    const float* base = x + (size_t)c * HW + (size_t)(ti * TH) * W_ + tj * TW;
    const size_t bstride = (size_t)C_ * HW;

    float s = 0.f, s2 = 0.f;
    for (int i = tid; i < B_ * TH * 5; i += 256) {
        int b = i / (TH * 5);
        int r = i - b * (TH * 5);
        int y = r / 5, xq = r - y * 5;
        float4 v = *reinterpret_cast<const float4*>(
            &base[(size_t)b * bstride + y * W_ + xq * 4]);
        s  += (v.x + v.y) + (v.z + v.w);
        s2 += (v.x * v.x + v.y * v.y) + (v.z * v.z + v.w * v.w);
    }

    // weight pack for oc = c: row = tap*32 + ic
    for (int i = tid; i < 288; i += 256) {
        int ic = i / 9, tap = i - ic * 9;
        float w = conv_w[(((size_t)t * C_ + c) * C_ + ic) * 9 + tap];
        g_w2[t][(tap * 32 + ic) * 32 + c] = __float2half(w);
    }

    // warp-shuffle reduction
#pragma unroll
    for (int off = 16; off > 0; off >>= 1) {
        s  += __shfl_xor_sync(0xFFFFFFFFu, s,  off);
        s2 += __shfl_xor_sync(0xFFFFFFFFu, s2, off);
    }
    __shared__ float ws[8], ws2[8];
    if (lane == 0) { ws[wid] = s; ws2[wid] = s2; }
    __syncthreads();
    if (wid == 0) {
        s  = (lane < 8) ? ws[lane]  : 0.f;
        s2 = (lane < 8) ? ws2[lane] : 0.f;
#pragma unroll
        for (int off = 4; off > 0; off >>= 1) {
            s  += __shfl_xor_sync(0xFFFFFFFFu, s,  off);
            s2 += __shfl_xor_sync(0xFFFFFFFFu, s2, off);
        }
        if (lane == 0) {
            const float invN = 1.f / (float)(B_ * TH * TW);
            float mean = s * invN;
            float var  = s2 * invN - mean * mean;
            float sc = gamma[bid] * rsqrtf(var + EPS);
            d_scale[bid] = sc;
            d_shift[bid] = beta[bid] - mean * sc;
        }
    }
}

// ---------------------------------------------------------------------------
// Kernel 2: per-(tile, batch) implicit-GEMM 3x3 conv via fp16 mma.sync.
// R13 main loop + smem-staged COALESCED epilogue (reuses dead h/w smem).
// ---------------------------------------------------------------------------
__global__ __launch_bounds__(NTHREADS, 2) void conv_kernel(
    const float* __restrict__ x,
    const float* __restrict__ conv_b,
    float* __restrict__ out)
{
    extern __shared__ char smem[];
    const uint32_t sbase = smem_u32(smem);
    const uint32_t hb = (sbase + 1023u) & ~1023u;
    const uint32_t wb = hb + H_BYTES;
    char* hptr = smem + (hb - sbase);
    char* wptr = smem + (wb - sbase);
    float* sscale = reinterpret_cast<float*>(smem + (wb - sbase) + W_BYTES);
    float* sshift = sscale + 32;
    float* sbias  = sshift + 32;

    const int bid = blockIdx.x;     // t*32 + b
    const int t = bid >> 5;
    const int b = bid & 31;
    const int ti = t >> 3, tj = t & 7;
    const int tid = threadIdx.x;
    const int warp = tid >> 5;
    const int lane = tid & 31;

    // ---- stage BN params + conv bias ----
    if (tid < 32) {
        sscale[tid] = d_scale[t * C_ + tid];
        sshift[tid] = d_shift[t * C_ + tid];
        sbias[tid]  = conv_b[t * C_ + tid];
    }

    // ---- zero h region (halo must be 0) ----
    {
        uint4 z = make_uint4(0, 0, 0, 0);
        uint4* hz = reinterpret_cast<uint4*>(hptr);
        for (int i = tid; i < H_BYTES / 16; i += NTHREADS) hz[i] = z;
    }

    // ---- copy fp16 weights: 288 rows x 64B content (2 x 32B chunks) ----
    {
        const uint4* gsrc = reinterpret_cast<const uint4*>(g_w2[t]);
        uint4* wdst = reinterpret_cast<uint4*>(wptr);
        for (int i = tid; i < 288 * 2; i += NTHREADS) {
            int row = i >> 1, hf = i & 1;
            wdst[(row * HSTRIDE + hf * 32) >> 4]       = gsrc[(row * 64 + hf * 32) >> 4];
            wdst[((row * HSTRIDE + hf * 32) >> 4) + 1] = gsrc[((row * 64 + hf * 32) >> 4) + 1];
        }
    }
    __syncthreads();

    // ---- prologue: thread = 4 channels x 1 pixel -> one STS.64 ----
    const size_t xtile = ((size_t)b * C_) * HW + (size_t)(ti * TH) * W_ + tj * TW;
    for (int i = tid; i < 8 * TH * TW; i += NTHREADS) {   // 3200 work items
        int p  = i % 400;          // pixel
        int cq = i / 400;          // channel quad
        int py = p / 20, px = p - py * 20;
        int c0 = cq * 4;
        const float* xp = &x[xtile + (size_t)c0 * HW + py * W_ + px];
        uint32_t hrow = (uint32_t)((py + 1) * 22 + px + 1) * HSTRIDE;
        __half hq[4];
#pragma unroll
        for (int j = 0; j < 4; j++) {
            float f = fmaxf(fmaf(xp[(size_t)j * HW], sscale[c0 + j], sshift[c0 + j]), 0.f);
            hq[j] = __float2half(f);
        }
        *reinterpret_cast<uint64_t*>(hptr + hrow + cq * 8) = *reinterpret_cast<uint64_t*>(hq);
    }
    __syncthreads();

    // ---- warp-level implicit GEMM: warp w owns tiles {2w, 2w+1} ----
    const int li   = lane & 7;
    const int sel8 = (lane >> 3) & 1;
    const int selk = (lane >> 4) & 1;
    const int tg   = lane & 3;
    const int g    = lane >> 2;

    const int mt0 = 2 * warp;
    const int mt1 = mt0 + 1;

    int pr0, pr1;
    {
        int m = mt0 * 16 + li + sel8 * 8;
        int my = m / 20;
        pr0 = my * 22 + (m - my * 20);
    }
    {
        int mm = mt1 * 16 + li + sel8 * 8;
        if (mm > 399) mm = 399;                  // dummy tile 25: clamp reads
        int my = mm / 20;
        pr1 = my * 22 + (mm - my * 20);
    }

    float acc0[4][4], acc1[4][4];
#pragma unroll
    for (int j = 0; j < 4; j++)
#pragma unroll
        for (int k = 0; k < 4; k++) { acc0[j][k] = 0.f; acc1[j][k] = 0.f; }

#pragma unroll 1
    for (int tap = 0; tap < 9; tap++) {
        const int dyx = (tap / 3) * 22 + (tap % 3);
#pragma unroll
        for (int kc = 0; kc < 2; kc++) {
            // ---- B fragments: once per (tap,kc), shared by both tiles ----
            const uint32_t brow = wb
                + (uint32_t)(tap * 32 + kc * 16 + li + sel8 * 8) * HSTRIDE;
            const uint32_t cb_ = (uint32_t)selk * 16;
            uint32_t bf[8];
            ldm_x4_t(brow + cb_,       bf[0], bf[1], bf[2], bf[3]);
            ldm_x4_t(brow + cb_ + 32,  bf[4], bf[5], bf[6], bf[7]);

            const uint32_t ca = (uint32_t)(kc * 2 + selk) * 16;

            // ---- tile 0 ----
            {
                const uint32_t arow = hb + (uint32_t)(pr0 + dyx) * HSTRIDE;
                uint32_t a0, a1, a2, a3;
                ldm_x4(arow + ca, a0, a1, a2, a3);
#pragma unroll
                for (int j = 0; j < 4; j++)
                    mma16816(acc0[j], a0, a1, a2, a3, bf[2 * j], bf[2 * j + 1]);
            }
            // ---- tile 1 ----
            {
                const uint32_t arow = hb + (uint32_t)(pr1 + dyx) * HSTRIDE;
                uint32_t a0, a1, a2, a3;
                ldm_x4(arow + ca, a0, a1, a2, a3);
#pragma unroll
                for (int j = 0; j < 4; j++)
                    mma16816(acc1[j], a0, a1, a2, a3, bf[2 * j], bf[2 * j + 1]);
            }
        }
    }

    // ---- epilogue stage 1: fragments -> smem staging [32 oc][404] ----
    __syncthreads();                  // h/w smem now dead; reuse as staging
    float* stg = reinterpret_cast<float*>(hptr);

#pragma unroll 1
    for (int tt = 0; tt < 2; tt++) {
        const int mt = (tt == 0) ? mt0 : mt1;
        const int m0 = mt * 16;
        if (m0 >= 400) break;                    // dummy tile: no stores
        const int p0 = m0 + g;
        const int p1 = p0 + 8;
        float (*ac)[4] = (tt == 0) ? acc0 : acc1;
#pragma unroll
        for (int j = 0; j < 4; j++) {
            const int oc = j * 8 + 2 * tg;
            stg[oc * STG_STRIDE + p0]       = ac[j][0];
            stg[(oc + 1) * STG_STRIDE + p0] = ac[j][1];
            stg[oc * STG_STRIDE + p1]       = ac[j][2];
            stg[(oc + 1) * STG_STRIDE + p1] = ac[j][3];
        }
    }
    __syncthreads();

    // ---- epilogue stage 2: coalesced bias + residual + store ----
    const size_t bb = (size_t)b * C_ * HW;
    const int gtile = (ti * TH) * W_ + tj * TW;
#pragma unroll 1
    for (int i = tid; i < 8 * 100; i += NTHREADS) {   // 800 float4 items
        int oc = i / 25;            // 25 float4 per oc... no: 100 per oc? fix below
        int r  = i - oc * 25;
        // NOTE: 400 px = 100 float4; use 100 per oc => i < 32*100 = 3200
        (void)r;
        break;
    }
    for (int i = tid; i < 32 * 100; i += NTHREADS) {  // 3200 float4 items
        int oc = i / 100;
        int r  = i - oc * 100;
        int y  = r / 5, xq = r - y * 5;
        float4 a = *reinterpret_cast<const float4*>(
            &stg[oc * STG_STRIDE + y * 20 + xq * 4]);
        const size_t o = bb + (size_t)oc * HW + (size_t)(gtile + y * W_ + xq * 4);
        float4 xr = *reinterpret_cast<const float4*>(&x[o]);
        float cbv = sbias[oc];
        float4 res;
        res.x = a.x + cbv + xr.x;
        res.y = a.y + cbv + xr.y;
        res.z = a.z + cbv + xr.z;
        res.w = a.w + cbv + xr.w;
        *reinterpret_cast<float4*>(&out[o]) = res;
    }
}

// ---------------------------------------------------------------------------
extern "C" void kernel_launch(void* const* d_in, const int* in_sizes, int n_in,
                              void* d_out, int out_size)
{
    const float* x      = (const float*)d_in[0];
    const float* gamma  = (const float*)d_in[1];
    const float* beta   = (const float*)d_in[2];
    const float* conv_w = (const float*)d_in[3];
    const float* conv_b = (const float*)d_in[4];
    float* out = (float*)d_out;

    bn_stats_kernel<<<NT * C_, 256>>>(x, gamma, beta, conv_w);

    cudaFuncSetAttribute(conv_kernel,
                         cudaFuncAttributeMaxDynamicSharedMemorySize, SMEM_REQ);
    conv_kernel<<<NT * B_, NTHREADS, SMEM_REQ>>>(x, conv_b, out);
}